// round 6
// baseline (speedup 1.0000x reference)
#include <cuda_runtime.h>
#include <cuda_bf16.h>
#include <math.h>
#include <stdint.h>

#define Bsz 8
#define Lsz 2048
#define Dsz 256
#define NPGC 4
#define NS4 4
#define EPS_T 1.1920929e-07f
#define EPS_C 1e-8f
#define ML (Bsz*Lsz)

typedef __nv_bfloat16 bf16;
typedef __nv_bfloat162 bf162;

// ---------------- scratch (static __device__, no allocs) ----------------
__device__ float g_h [ML*Dsz];
__device__ float g_b1[ML*2*Dsz];
__device__ float g_b2[ML*Dsz];
__device__ float g_b3[ML*Dsz];
__device__ float g_b4[ML*Dsz];
__device__ float g_lam_r[Dsz*32], g_lam_i[Dsz*32], g_cm_r[Dsz*32], g_cm_i[Dsz*32];

// bf16 split activation buffers
__device__ bf16 g_xh[ML*Dsz], g_xl[ML*Dsz];
__device__ bf16 g_yh[ML*Dsz], g_yl[ML*Dsz];
__device__ bf16 g_qh[ML*Dsz], g_ql[ML*Dsz];
__device__ bf16 g_kh[ML*Dsz], g_kl[ML*Dsz];

// bf16 split weights (all K-major [N,K])
#define OFF_PIN  0                   // 4 * 512*256
#define OFF_POUT 524288              // 4 * 256*256
#define OFF_S4   786432              // 4 * 512*256
#define OFF_Q    1310720             // 256*256
#define OFF_K    1376256             // 256*256
#define OFF_DB   1441792             // 128*256
#define OFF_BIN  1474560             // 64*256
#define WTOT     1490944
__device__ bf16 g_wh[WTOT], g_wl[WTOT];

__device__ __forceinline__ float gelu_f(float x) {
    return 0.5f * x * (1.f + erff(x * 0.70710678118654752f));
}
__device__ __forceinline__ void split2(float v, bf16& h, bf16& l) {
    h = __float2bfloat16_rn(v);
    l = __float2bfloat16_rn(v - __bfloat162float(h));
}
__device__ __forceinline__ void mma_bf16(float* d, const uint32_t* a, const uint32_t* b) {
    asm volatile(
        "mma.sync.aligned.m16n8k16.row.col.f32.bf16.bf16.f32 "
        "{%0,%1,%2,%3},{%4,%5,%6,%7},{%8,%9},{%0,%1,%2,%3};"
        : "+f"(d[0]), "+f"(d[1]), "+f"(d[2]), "+f"(d[3])
        : "r"(a[0]), "r"(a[1]), "r"(a[2]), "r"(a[3]), "r"(b[0]), "r"(b[1]));
}
__device__ __forceinline__ void cp16(void* dst, const void* src, int sz) {
    uint32_t d = (uint32_t)__cvta_generic_to_shared(dst);
    asm volatile("cp.async.cg.shared.global [%0], [%1], 16, %2;" :: "r"(d), "l"(src), "r"(sz));
}

// ---------------- encoder: h = x(.,4) @ enc_w + enc_b, also emits split ----------------
__global__ void encoder_k(const float* __restrict__ x, const float* __restrict__ w,
                          const float* __restrict__ b, float* __restrict__ h,
                          bf16* __restrict__ oh, bf16* __restrict__ ol) {
    long m = blockIdx.x;
    int d = threadIdx.x;
    const float* xr = x + m * 4;
    float acc = b[d];
    #pragma unroll
    for (int i = 0; i < 4; i++) acc = fmaf(xr[i], w[i * 256 + d], acc);
    h[m * 256 + d] = acc;
    bf16 hh, ll; split2(acc, hh, ll);
    oh[m * 256 + d] = hh; ol[m * 256 + d] = ll;
}

// ---------------- bf16 3-term split GEMM, cp.async double-buffered ----------------
// A: [M,K] K-major split (Ah,Al). B: [N,K] K-major split. K % 16 == 0, M % 128 == 0.
#define TBK 16
#define KP 24
__global__ __launch_bounds__(256, 2)
void gemm_bf(const bf16* __restrict__ Ah_, const bf16* __restrict__ Al_,
             const bf16* __restrict__ Bh_, const bf16* __restrict__ Bl_,
             const float* __restrict__ bias,
             float* __restrict__ C, bf16* __restrict__ Ch, bf16* __restrict__ Cl,
             int M, int N, int K,
             long long As_b, long long Bs_b, long long Cs_b, long long Cs_m,
             float alpha, int act) {
    __shared__ __align__(16) bf16 sA[2][2][128][KP];
    __shared__ __align__(16) bf16 sB[2][2][128][KP];
    int batch = blockIdx.z;
    const bf16* Ah = Ah_ + (long long)batch * As_b;
    const bf16* Al = Al_ + (long long)batch * As_b;
    const bf16* Bh = Bh_ + (long long)batch * Bs_b;
    const bf16* Bl = Bl_ + (long long)batch * Bs_b;
    int m0 = blockIdx.y * 128, n0 = blockIdx.x * 128;
    int tid = threadIdx.x;
    int w = tid >> 5, lane = tid & 31;
    int wm = (w & 1) * 64, wn = (w >> 1) * 32;
    int gid = lane >> 2, tig = lane & 3;

    float acc[4][4][4];
    #pragma unroll
    for (int i = 0; i < 4; i++)
        #pragma unroll
        for (int j = 0; j < 4; j++)
            #pragma unroll
            for (int r = 0; r < 4; r++) acc[i][j][r] = 0.f;

    int row = tid >> 1;
    int off = (tid & 1) * 8;
    int bn = n0 + row;
    int bok = (bn < N) ? 16 : 0;
    long long bro = (long long)((bn < N) ? bn : 0) * K;
    long long aro = (long long)(m0 + row) * K;

    auto load_tile = [&](int buf, int kt) {
        int k0 = kt * TBK + off;
        cp16(&sA[buf][0][row][off], Ah + aro + k0, 16);
        cp16(&sA[buf][1][row][off], Al + aro + k0, 16);
        cp16(&sB[buf][0][row][off], Bh + bro + k0, bok);
        cp16(&sB[buf][1][row][off], Bl + bro + k0, bok);
    };

    int T = K / TBK;
    load_tile(0, 0);
    asm volatile("cp.async.commit_group;");
    load_tile(1, 1);
    asm volatile("cp.async.commit_group;");

    for (int t = 0; t < T; t++) {
        if (t < T - 1) asm volatile("cp.async.wait_group 1;");
        else           asm volatile("cp.async.wait_group 0;");
        __syncthreads();
        int buf = t & 1;
        {
            uint32_t bhf[4][2], blf[4][2];
            #pragma unroll
            for (int nf = 0; nf < 4; nf++) {
                int nc = wn + nf * 8 + gid;
                bhf[nf][0] = *(const uint32_t*)&sB[buf][0][nc][2 * tig];
                bhf[nf][1] = *(const uint32_t*)&sB[buf][0][nc][2 * tig + 8];
                blf[nf][0] = *(const uint32_t*)&sB[buf][1][nc][2 * tig];
                blf[nf][1] = *(const uint32_t*)&sB[buf][1][nc][2 * tig + 8];
            }
            #pragma unroll
            for (int mf = 0; mf < 4; mf++) {
                int mr = wm + mf * 16 + gid;
                uint32_t ah[4], al[4];
                ah[0] = *(const uint32_t*)&sA[buf][0][mr    ][2 * tig];
                ah[1] = *(const uint32_t*)&sA[buf][0][mr + 8][2 * tig];
                ah[2] = *(const uint32_t*)&sA[buf][0][mr    ][2 * tig + 8];
                ah[3] = *(const uint32_t*)&sA[buf][0][mr + 8][2 * tig + 8];
                al[0] = *(const uint32_t*)&sA[buf][1][mr    ][2 * tig];
                al[1] = *(const uint32_t*)&sA[buf][1][mr + 8][2 * tig];
                al[2] = *(const uint32_t*)&sA[buf][1][mr    ][2 * tig + 8];
                al[3] = *(const uint32_t*)&sA[buf][1][mr + 8][2 * tig + 8];
                #pragma unroll
                for (int nf = 0; nf < 4; nf++) {
                    mma_bf16(acc[mf][nf], ah, blf[nf]);
                    mma_bf16(acc[mf][nf], al, bhf[nf]);
                    mma_bf16(acc[mf][nf], ah, bhf[nf]);
                }
            }
        }
        __syncthreads();
        if (t + 2 < T) {
            load_tile(buf, t + 2);
            asm volatile("cp.async.commit_group;");
        }
    }

    // epilogue
    float* Cb = C ? C + (long long)batch * Cs_b : (float*)0;
    #pragma unroll
    for (int mf = 0; mf < 4; mf++) {
        #pragma unroll
        for (int nf = 0; nf < 4; nf++) {
            int col = n0 + wn + nf * 8 + 2 * tig;
            if (col >= N) continue;
            int row0 = m0 + wm + mf * 16 + gid;
            float v[4];
            #pragma unroll
            for (int r = 0; r < 4; r++) {
                float t = acc[mf][nf][r] * alpha;
                if (bias) t += bias[col + (r & 1)];
                if (act == 1) t = gelu_f(t);
                v[r] = t;
            }
            if (Cb) {
                Cb[(long long)row0 * Cs_m + col]       = v[0];
                Cb[(long long)row0 * Cs_m + col + 1]   = v[1];
                Cb[(long long)(row0 + 8) * Cs_m + col]     = v[2];
                Cb[(long long)(row0 + 8) * Cs_m + col + 1] = v[3];
            }
            if (Ch) {
                bf16 h0,l0,h1,l1;
                split2(v[0], h0, l0); split2(v[1], h1, l1);
                bf162 ph; ph.x = h0; ph.y = h1;
                bf162 pl; pl.x = l0; pl.y = l1;
                *(bf162*)&Ch[(long long)row0 * N + col] = ph;
                *(bf162*)&Cl[(long long)row0 * N + col] = pl;
                split2(v[2], h0, l0); split2(v[3], h1, l1);
                ph.x = h0; ph.y = h1; pl.x = l0; pl.y = l1;
                *(bf162*)&Ch[(long long)(row0 + 8) * N + col] = ph;
                *(bf162*)&Cl[(long long)(row0 + 8) * N + col] = pl;
            }
        }
    }
}

// ---------------- weight transpose + split: in [K,N] n-contig -> out [N,K] ----------------
__global__ void wsplit_T(const float* __restrict__ w, bf16* __restrict__ oh,
                         bf16* __restrict__ ol, int K, int N) {
    __shared__ float t[32][33];
    int n0 = blockIdx.x * 32, k0 = blockIdx.y * 32;
    int tx = threadIdx.x, ty = threadIdx.y;
    #pragma unroll
    for (int j = 0; j < 32; j += 8)
        t[ty + j][tx] = w[(long)(k0 + ty + j) * N + n0 + tx];
    __syncthreads();
    #pragma unroll
    for (int j = 0; j < 32; j += 8) {
        float v = t[tx][ty + j];
        bf16 hh, ll; split2(v, hh, ll);
        long o = (long)(n0 + ty + j) * K + k0 + tx;
        oh[o] = hh; ol[o] = ll;
    }
}

// ---------------- plain vectorized split ----------------
__global__ void split_k(const float* __restrict__ in, bf16* __restrict__ oh,
                        bf16* __restrict__ ol, long n4) {
    long i = (long)blockIdx.x * 256 + threadIdx.x;
    if (i >= n4) return;
    float4 v = ((const float4*)in)[i];
    bf16 h0,l0,h1,l1,h2,l2,h3,l3;
    split2(v.x,h0,l0); split2(v.y,h1,l1); split2(v.z,h2,l2); split2(v.w,h3,l3);
    bf162 a,b;
    a.x=h0; a.y=h1; b.x=h2; b.y=h3;
    ((bf162*)oh)[i*2] = a; ((bf162*)oh)[i*2+1] = b;
    a.x=l0; a.y=l1; b.x=l2; b.y=l3;
    ((bf162*)ol)[i*2] = a; ((bf162*)ol)[i*2+1] = b;
}

// ---------------- RMSNorm (fp32 out OR split out) ----------------
__global__ void rmsnorm_k(const float* __restrict__ in, const float* __restrict__ w,
                          float* __restrict__ out, bf16* __restrict__ oh, bf16* __restrict__ ol,
                          int ncols, float eps) {
    long row = blockIdx.x;
    const float* r = in + row * (long)ncols;
    float ss = 0.f;
    for (int c = threadIdx.x; c < ncols; c += blockDim.x) { float v = r[c]; ss = fmaf(v, v, ss); }
    #pragma unroll
    for (int o = 16; o; o >>= 1) ss += __shfl_xor_sync(~0u, ss, o);
    __shared__ float sh[32];
    int wid = threadIdx.x >> 5, lane = threadIdx.x & 31;
    if (lane == 0) sh[wid] = ss;
    __syncthreads();
    int nw = blockDim.x >> 5;
    if (wid == 0) {
        ss = (lane < nw) ? sh[lane] : 0.f;
        #pragma unroll
        for (int o = 16; o; o >>= 1) ss += __shfl_xor_sync(~0u, ss, o);
        if (lane == 0) sh[0] = ss;
    }
    __syncthreads();
    float scale = rsqrtf(sh[0] / (float)ncols + eps);
    for (int c = threadIdx.x; c < ncols; c += blockDim.x) {
        float v = r[c] * scale * w[c];
        if (out) out[row * (long)ncols + c] = v;
        if (oh) { bf16 hh, ll; split2(v, hh, ll); oh[row*(long)ncols+c]=hh; ol[row*(long)ncols+c]=ll; }
    }
}

// ---------------- PGC conv3 + gate ----------------
__global__ void conv_gate_k(const float* __restrict__ xv, const float* __restrict__ cw,
                            const float* __restrict__ cb, float* __restrict__ g) {
    long bl = blockIdx.x;
    int l = (int)(bl & (Lsz - 1));
    int e = threadIdx.x;
    const float* base = xv + bl * 512;
    float xm = (l > 0)       ? base[-512 + e] : 0.f;
    float xc = base[e];
    float xp = (l < Lsz - 1) ? base[ 512 + e] : 0.f;
    float v  = base[256 + e];
    float w0 = cw[e * 3], w1 = cw[e * 3 + 1], w2 = cw[e * 3 + 2];
    float conv = fmaf(w0, xm, fmaf(w1, xc, fmaf(w2, xp, cb[e])));
    g[bl * 256 + e] = v * conv;
}

// ---------------- transpose (B,L,D) -> (B,D,L) fp32 ----------------
__global__ void transpose_LD(const float* __restrict__ in, float* __restrict__ out) {
    __shared__ float tile[32][33];
    int b = blockIdx.z;
    int l0 = blockIdx.x * 32, d0 = blockIdx.y * 32;
    #pragma unroll
    for (int j = 0; j < 32; j += 8)
        tile[threadIdx.y + j][threadIdx.x] =
            in[((long)b * Lsz + (l0 + threadIdx.y + j)) * Dsz + d0 + threadIdx.x];
    __syncthreads();
    #pragma unroll
    for (int j = 0; j < 32; j += 8)
        out[((long)b * Dsz + (d0 + threadIdx.y + j)) * Lsz + l0 + threadIdx.x] =
            tile[threadIdx.x][threadIdx.y + j];
}

// ---------------- transpose+split (B,D,L) -> (B,L,D) bf16 hi/lo ----------------
__global__ void tsplit_DL(const float* __restrict__ in, bf16* __restrict__ oh,
                          bf16* __restrict__ ol) {
    __shared__ float tile[32][33];
    int b = blockIdx.z;
    int d0 = blockIdx.x * 32, l0 = blockIdx.y * 32;
    #pragma unroll
    for (int j = 0; j < 32; j += 8)
        tile[threadIdx.y + j][threadIdx.x] =
            in[((long)b * Dsz + (d0 + threadIdx.y + j)) * Lsz + l0 + threadIdx.x];
    __syncthreads();
    #pragma unroll
    for (int j = 0; j < 32; j += 8) {
        float v = tile[threadIdx.x][threadIdx.y + j];
        bf16 hh, ll; split2(v, hh, ll);
        long o = ((long)b * Lsz + (l0 + threadIdx.y + j)) * Dsz + d0 + threadIdx.x;
        oh[o] = hh; ol[o] = ll;
    }
}

// ---------------- S4D parameter precompute ----------------
__global__ void s4_pre_k(const float* __restrict__ C_ri, const float* __restrict__ log_dt,
                         const float* __restrict__ logAr, const float* __restrict__ Aim,
                         float* __restrict__ lam_r, float* __restrict__ lam_i,
                         float* __restrict__ cm_r, float* __restrict__ cm_i) {
    int idx = blockIdx.x * blockDim.x + threadIdx.x;
    if (idx >= Dsz * 32) return;
    int h = idx >> 5;
    float dt = expf(log_dt[h]);
    float Ar = -expf(logAr[idx]);
    float Ai = Aim[idx];
    float dr = Ar * dt, di = Ai * dt;
    float er = expf(dr);
    float lr = er * cosf(di), li = er * sinf(di);
    lam_r[idx] = lr; lam_i[idx] = li;
    float Er = lr - 1.f, Ei = li;
    float den = Ar * Ar + Ai * Ai;
    float qr = (Er * Ar + Ei * Ai) / den;
    float qi = (Ei * Ar - Er * Ai) / den;
    float Cr = C_ri[idx * 2], Ci = C_ri[idx * 2 + 1];
    cm_r[idx] = Cr * qr - Ci * qi;
    cm_i[idx] = Cr * qi + Ci * qr;
}

// ---------------- S4D diagonal recurrence ----------------
__global__ void s4_scan_k(const float* __restrict__ u,
                          const float* __restrict__ lam_r, const float* __restrict__ lam_i,
                          const float* __restrict__ cm_r, const float* __restrict__ cm_i,
                          const float* __restrict__ Dp, float* __restrict__ y) {
    int gw = (blockIdx.x * blockDim.x + threadIdx.x) >> 5;
    int lane = threadIdx.x & 31;
    int b = gw >> 8, h = gw & 255;
    int idx = h * 32 + lane;
    float lr = lam_r[idx], li = lam_i[idx];
    float cr = cm_r[idx],  ci = cm_i[idx];
    float dp = Dp[h];
    const float* up = u + ((long)b * Dsz + h) * Lsz;
    float*       yp = y + ((long)b * Dsz + h) * Lsz;
    float sr = 0.f, si = 0.f;
    #pragma unroll 4
    for (int l = 0; l < Lsz; l++) {
        float uv = __ldg(up + l);
        float nsr = fmaf(lr, sr, fmaf(-li, si, uv));
        float nsi = fmaf(lr, si, li * sr);
        sr = nsr; si = nsi;
        float c = cr * sr - ci * si;
        c += __shfl_xor_sync(~0u, c, 16);
        c += __shfl_xor_sync(~0u, c, 8);
        c += __shfl_xor_sync(~0u, c, 4);
        c += __shfl_xor_sync(~0u, c, 2);
        c += __shfl_xor_sync(~0u, c, 1);
        if (lane == 0) {
            float yv = fmaf(dp, uv, 2.f * c);
            yp[l] = gelu_f(yv);
        }
    }
}

// ---------------- GLU + residual ----------------
__global__ void glu_res_k(const float* __restrict__ z, float* __restrict__ h) {
    long idx = (long)blockIdx.x * 256 + threadIdx.x;
    long row = idx >> 8;
    int o = (int)(idx & 255);
    float a = z[row * 512 + o];
    float g = z[row * 512 + 256 + o];
    h[idx] += a * (1.f / (1.f + expf(-g)));
}

// ---------------- small scalar GEMM (tiny N heads) ----------------
__global__ void gemm_small(const float* __restrict__ A, const float* __restrict__ Bm,
                           const float* __restrict__ bias, float* __restrict__ C,
                           int N, int K, long long Cs_m) {
    long m = blockIdx.x;
    int tid = threadIdx.x;
    const float* Ar = A + m * K;
    __shared__ float red[4][128];
    for (int n = 0; n < N; n++) {
        float s = 0.f;
        for (int k = tid; k < K; k += 128) s = fmaf(Ar[k], Bm[(long)k * N + n], s);
        red[n][tid] = s;
    }
    __syncthreads();
    if (tid < N) {
        float s = 0.f;
        #pragma unroll
        for (int i = 0; i < 128; i++) s += red[tid][i];
        C[m * Cs_m + tid] = s + bias[tid];
    }
}

// ---------------- unpaired column ----------------
__global__ void unpaired_k(const float* __restrict__ ub, float* __restrict__ out) {
    int idx = blockIdx.x * blockDim.x + threadIdx.x;
    out[(long)idx * 2054 + 2053] = ub[0];
}

// ---------------- host ----------------
static void gemm_bf_launch(const bf16* Ah, const bf16* Al, const bf16* Bh, const bf16* Bl,
                           const float* bias, float* C, bf16* Ch, bf16* Cl,
                           int M, int N, int K,
                           long long asb, long long bsb, long long csb, long long csm,
                           float alpha, int act, int batch) {
    dim3 grid((N + 127) / 128, M / 128, batch);
    gemm_bf<<<grid, 256>>>(Ah, Al, Bh, Bl, bias, C, Ch, Cl, M, N, K,
                           asb, bsb, csb, csm, alpha, act);
}

extern "C" void kernel_launch(void* const* d_in, const int* in_sizes, int n_in,
                              void* d_out, int out_size) {
    const float* x          = (const float*)d_in[0];
    const float* enc_w      = (const float*)d_in[1];
    const float* enc_b      = (const float*)d_in[2];
    const float* pgc_in_w   = (const float*)d_in[3];
    const float* pgc_in_b   = (const float*)d_in[4];
    const float* pgc_innorm = (const float*)d_in[5];
    const float* pgc_conv_w = (const float*)d_in[6];
    const float* pgc_conv_b = (const float*)d_in[7];
    const float* pgc_norm_w = (const float*)d_in[8];
    const float* pgc_out_w  = (const float*)d_in[9];
    const float* pgc_out_b  = (const float*)d_in[10];
    const float* s4_norm_w  = (const float*)d_in[11];
    const float* s4_Dp      = (const float*)d_in[12];
    const float* s4_C       = (const float*)d_in[13];
    const float* s4_log_dt  = (const float*)d_in[14];
    const float* s4_logAr   = (const float*)d_in[15];
    const float* s4_Aim     = (const float*)d_in[16];
    const float* s4_out_w   = (const float*)d_in[17];
    const float* s4_out_b   = (const float*)d_in[18];
    const float* db_w1      = (const float*)d_in[19];
    const float* db_b1      = (const float*)d_in[20];
    const float* db_w2      = (const float*)d_in[21];
    const float* db_b2      = (const float*)d_in[22];
    const float* bin_w1     = (const float*)d_in[23];
    const float* bin_b1     = (const float*)d_in[24];
    const float* bin_w2     = (const float*)d_in[25];
    const float* bin_b2     = (const float*)d_in[26];
    const float* q_w        = (const float*)d_in[27];
    const float* q_b        = (const float*)d_in[28];
    const float* k_w        = (const float*)d_in[29];
    const float* k_b        = (const float*)d_in[30];
    const float* ub         = (const float*)d_in[31];
    float* out = (float*)d_out;

    float *h, *b1, *b2, *b3, *b4, *lr, *li, *cr, *ci;
    bf16 *xh, *xl, *yh, *yl, *qh, *ql, *kh, *kl, *wh, *wl;
    cudaGetSymbolAddress((void**)&h,  g_h);
    cudaGetSymbolAddress((void**)&b1, g_b1);
    cudaGetSymbolAddress((void**)&b2, g_b2);
    cudaGetSymbolAddress((void**)&b3, g_b3);
    cudaGetSymbolAddress((void**)&b4, g_b4);
    cudaGetSymbolAddress((void**)&lr, g_lam_r);
    cudaGetSymbolAddress((void**)&li, g_lam_i);
    cudaGetSymbolAddress((void**)&cr, g_cm_r);
    cudaGetSymbolAddress((void**)&ci, g_cm_i);
    cudaGetSymbolAddress((void**)&xh, g_xh);
    cudaGetSymbolAddress((void**)&xl, g_xl);
    cudaGetSymbolAddress((void**)&yh, g_yh);
    cudaGetSymbolAddress((void**)&yl, g_yl);
    cudaGetSymbolAddress((void**)&qh, g_qh);
    cudaGetSymbolAddress((void**)&ql, g_ql);
    cudaGetSymbolAddress((void**)&kh, g_kh);
    cudaGetSymbolAddress((void**)&kl, g_kl);
    cudaGetSymbolAddress((void**)&wh, g_wh);
    cudaGetSymbolAddress((void**)&wl, g_wl);

    // ---- one-time weight conversion (per launch; cheap) ----
    dim3 tt(32, 8);
    for (int i = 0; i < NPGC; i++) {
        wsplit_T<<<dim3(512/32, 256/32), tt>>>(pgc_in_w + (long)i*131072,
                                               wh + OFF_PIN + (long)i*131072,
                                               wl + OFF_PIN + (long)i*131072, 256, 512);
        wsplit_T<<<dim3(256/32, 256/32), tt>>>(pgc_out_w + (long)i*65536,
                                               wh + OFF_POUT + (long)i*65536,
                                               wl + OFF_POUT + (long)i*65536, 256, 256);
    }
    split_k<<<(4*512*256/4 + 255)/256, 256>>>(s4_out_w, wh + OFF_S4, wl + OFF_S4, 4*512*256/4);
    wsplit_T<<<dim3(8, 8), tt>>>(q_w,   wh + OFF_Q,   wl + OFF_Q,   256, 256);
    wsplit_T<<<dim3(8, 8), tt>>>(k_w,   wh + OFF_K,   wl + OFF_K,   256, 256);
    wsplit_T<<<dim3(4, 8), tt>>>(db_w1, wh + OFF_DB,  wl + OFF_DB,  256, 128);
    wsplit_T<<<dim3(2, 8), tt>>>(bin_w1,wh + OFF_BIN, wl + OFF_BIN, 256, 64);

    // ---- encoder ----
    encoder_k<<<ML, 256>>>(x, enc_w, enc_b, h, xh, xl);

    // ---- PGC stack ----
    for (int i = 0; i < NPGC; i++) {
        gemm_bf_launch(xh, xl, wh + OFF_PIN + (long)i*131072, wl + OFF_PIN + (long)i*131072,
                       pgc_in_b + i*512, b1, 0, 0, ML, 512, 256, 0, 0, 0, 512, 1.f, 0, 1);
        rmsnorm_k<<<ML, 256>>>(b1, pgc_innorm + i*512, b1, 0, 0, 512, EPS_T);
        conv_gate_k<<<ML, 256>>>(b1, pgc_conv_w + i*768, pgc_conv_b + i*256, b2);
        rmsnorm_k<<<ML, 256>>>(b2, pgc_norm_w + i*256, 0, yh, yl, 256, EPS_T);
        gemm_bf_launch(yh, yl, wh + OFF_POUT + (long)i*65536, wl + OFF_POUT + (long)i*65536,
                       pgc_out_b + i*256, h, xh, xl, ML, 256, 256, 0, 0, 0, 256, 1.f, 0, 1);
    }

    // ---- S4D stack ----
    for (int i = 0; i < NS4; i++) {
        s4_pre_k<<<32, 256>>>(s4_C + (long)i*16384, s4_log_dt + i*256,
                              s4_logAr + (long)i*8192, s4_Aim + (long)i*8192,
                              lr, li, cr, ci);
        rmsnorm_k<<<ML, 256>>>(h, s4_norm_w + i*256, b2, 0, 0, 256, EPS_C);
        transpose_LD<<<dim3(Lsz/32, Dsz/32, Bsz), tt>>>(b2, b3);
        s4_scan_k<<<(Bsz * Dsz) / 4, 128>>>(b3, lr, li, cr, ci, s4_Dp + i*256, b4);
        tsplit_DL<<<dim3(Dsz/32, Lsz/32, Bsz), tt>>>(b4, xh, xl);
        gemm_bf_launch(xh, xl, wh + OFF_S4 + (long)i*131072, wl + OFF_S4 + (long)i*131072,
                       s4_out_b + i*512, b1, 0, 0, ML, 512, 256, 0, 0, 0, 512, 1.f, 0, 1);
        glu_res_k<<<ML, 256>>>(b1, h);
    }

    // final h split for heads
    split_k<<<(ML*256/4 + 255)/256, 256>>>(h, xh, xl, (long)ML*256/4);

    // ---- heads ----
    gemm_bf_launch(xh, xl, wh + OFF_DB, wl + OFF_DB, db_b1, b1, 0, 0,
                   ML, 128, 256, 0, 0, 0, 128, 1.f, 1, 1);
    gemm_small<<<ML, 128>>>(b1, db_w2, db_b2, out, 3, 128, 2054);
    gemm_bf_launch(xh, xl, wh + OFF_BIN, wl + OFF_BIN, bin_b1, b1, 0, 0,
                   ML, 64, 256, 0, 0, 0, 64, 1.f, 1, 1);
    gemm_small<<<ML, 128>>>(b1, bin_w2, bin_b2, out + 3, 2, 64, 2054);
    gemm_bf_launch(xh, xl, wh + OFF_Q, wl + OFF_Q, q_b, 0, qh, ql,
                   ML, 256, 256, 0, 0, 0, 256, 1.f, 0, 1);
    gemm_bf_launch(xh, xl, wh + OFF_K, wl + OFF_K, k_b, 0, kh, kl,
                   ML, 256, 256, 0, 0, 0, 256, 1.f, 0, 1);
    // scores = q @ k^T / 16 -> out[:, :, 5:5+2048], batched
    gemm_bf_launch(qh, ql, kh, kl, 0, out + 5, 0, 0,
                   Lsz, Lsz, 256,
                   (long long)Lsz*256, (long long)Lsz*256, (long long)Lsz*2054, 2054,
                   0.0625f, 0, Bsz);
    unpaired_k<<<ML/256, 256>>>(ub, out);
}

// round 7
// speedup vs baseline: 1.5021x; 1.5021x over previous
#include <cuda_runtime.h>
#include <cuda_bf16.h>
#include <math.h>
#include <stdint.h>

#define Bsz 8
#define Lsz 2048
#define Dsz 256
#define NPGC 4
#define NS4 4
#define EPS_T 1.1920929e-07f
#define EPS_C 1e-8f
#define ML (Bsz*Lsz)

typedef __nv_bfloat16 bf16;
typedef __nv_bfloat162 bf162;

// ---------------- scratch (static __device__, no allocs) ----------------
__device__ float g_h [ML*Dsz];
__device__ float g_b1[ML*2*Dsz];
__device__ float g_b2[ML*Dsz];
__device__ float g_b3[ML*Dsz];
__device__ float g_b4[ML*Dsz];
__device__ float g_lam_r[Dsz*32], g_lam_i[Dsz*32], g_cm_r[Dsz*32], g_cm_i[Dsz*32];

// bf16 split activation buffers
__device__ bf16 g_xh[ML*Dsz], g_xl[ML*Dsz];
__device__ bf16 g_yh[ML*Dsz], g_yl[ML*Dsz];
__device__ bf16 g_qh[ML*Dsz], g_ql[ML*Dsz];
__device__ bf16 g_kh[ML*Dsz], g_kl[ML*Dsz];

// bf16 split weights (all K-major [N,K])
#define OFF_PIN  0
#define OFF_POUT 524288
#define OFF_S4   786432
#define OFF_Q    1310720
#define OFF_K    1376256
#define OFF_DB   1441792
#define OFF_BIN  1474560
#define WTOT     1490944
__device__ bf16 g_wh[WTOT], g_wl[WTOT];

__device__ __forceinline__ float gelu_f(float x) {
    return 0.5f * x * (1.f + erff(x * 0.70710678118654752f));
}
__device__ __forceinline__ void split2(float v, bf16& h, bf16& l) {
    h = __float2bfloat16_rn(v);
    l = __float2bfloat16_rn(v - __bfloat162float(h));
}
__device__ __forceinline__ void mma_bf16(float* d, const uint32_t* a, const uint32_t* b) {
    asm volatile(
        "mma.sync.aligned.m16n8k16.row.col.f32.bf16.bf16.f32 "
        "{%0,%1,%2,%3},{%4,%5,%6,%7},{%8,%9},{%0,%1,%2,%3};"
        : "+f"(d[0]), "+f"(d[1]), "+f"(d[2]), "+f"(d[3])
        : "r"(a[0]), "r"(a[1]), "r"(a[2]), "r"(a[3]), "r"(b[0]), "r"(b[1]));
}

// ---------------- encoder ----------------
__global__ void encoder_k(const float* __restrict__ x, const float* __restrict__ w,
                          const float* __restrict__ b, float* __restrict__ h,
                          bf16* __restrict__ oh, bf16* __restrict__ ol) {
    long m = blockIdx.x;
    int d = threadIdx.x;
    const float* xr = x + m * 4;
    float acc = b[d];
    #pragma unroll
    for (int i = 0; i < 4; i++) acc = fmaf(xr[i], w[i * 256 + d], acc);
    h[m * 256 + d] = acc;
    bf16 hh, ll; split2(acc, hh, ll);
    oh[m * 256 + d] = hh; ol[m * 256 + d] = ll;
}

// ---------------- bf16 3-term split GEMM, pre-split operands, reg-prefetch ----------------
// A: [M,K] K-major split. B: [N,K] K-major split. K % 16 == 0, M % 128 == 0.
#define TBK 16
#define KP 24
__global__ __launch_bounds__(256, 2)
void gemm_bf(const bf16* __restrict__ Ah_, const bf16* __restrict__ Al_,
             const bf16* __restrict__ Bh_, const bf16* __restrict__ Bl_,
             const float* __restrict__ bias,
             float* __restrict__ C, bf16* __restrict__ Ch, bf16* __restrict__ Cl,
             int M, int N, int K,
             long long As_b, long long Bs_b, long long Cs_b, long long Cs_m,
             float alpha, int act) {
    __shared__ __align__(16) bf16 sAh[128][KP], sAl[128][KP];
    __shared__ __align__(16) bf16 sBh[128][KP], sBl[128][KP];
    int batch = blockIdx.z;
    const bf16* Ah = Ah_ + (long long)batch * As_b;
    const bf16* Al = Al_ + (long long)batch * As_b;
    const bf16* Bh = Bh_ + (long long)batch * Bs_b;
    const bf16* Bl = Bl_ + (long long)batch * Bs_b;
    int m0 = blockIdx.y * 128, n0 = blockIdx.x * 128;
    int tid = threadIdx.x;
    int w = tid >> 5, lane = tid & 31;
    int wm = (w & 1) * 64, wn = (w >> 1) * 32;
    int gid = lane >> 2, tig = lane & 3;

    float acc[4][4][4];
    #pragma unroll
    for (int i = 0; i < 4; i++)
        #pragma unroll
        for (int j = 0; j < 4; j++)
            #pragma unroll
            for (int r = 0; r < 4; r++) acc[i][j][r] = 0.f;

    int row  = tid >> 1;
    int off8 = (tid & 1) * 8;          // bf16 element offset within k-tile
    int bn = n0 + row;
    long long aro = (long long)(m0 + row) * K;
    long long bro = (long long)((bn < N) ? bn : 0) * K;

    uint4 ra_h, ra_l, rb_h, rb_l;
    auto fetch = [&](int kt) {
        int k0 = kt * TBK + off8;
        ra_h = *(const uint4*)(Ah + aro + k0);
        ra_l = *(const uint4*)(Al + aro + k0);
        rb_h = *(const uint4*)(Bh + bro + k0);
        rb_l = *(const uint4*)(Bl + bro + k0);
    };

    int T = K / TBK;
    fetch(0);
    for (int t = 0; t < T; t++) {
        *(uint4*)&sAh[row][off8] = ra_h;
        *(uint4*)&sAl[row][off8] = ra_l;
        *(uint4*)&sBh[row][off8] = rb_h;
        *(uint4*)&sBl[row][off8] = rb_l;
        __syncthreads();
        if (t + 1 < T) fetch(t + 1);

        uint32_t bhf[4][2], blf[4][2];
        #pragma unroll
        for (int nf = 0; nf < 4; nf++) {
            int nc = wn + nf * 8 + gid;
            bhf[nf][0] = *(const uint32_t*)&sBh[nc][2 * tig];
            bhf[nf][1] = *(const uint32_t*)&sBh[nc][2 * tig + 8];
            blf[nf][0] = *(const uint32_t*)&sBl[nc][2 * tig];
            blf[nf][1] = *(const uint32_t*)&sBl[nc][2 * tig + 8];
        }
        #pragma unroll
        for (int mf = 0; mf < 4; mf++) {
            int mr = wm + mf * 16 + gid;
            uint32_t ah[4], al[4];
            ah[0] = *(const uint32_t*)&sAh[mr    ][2 * tig];
            ah[1] = *(const uint32_t*)&sAh[mr + 8][2 * tig];
            ah[2] = *(const uint32_t*)&sAh[mr    ][2 * tig + 8];
            ah[3] = *(const uint32_t*)&sAh[mr + 8][2 * tig + 8];
            al[0] = *(const uint32_t*)&sAl[mr    ][2 * tig];
            al[1] = *(const uint32_t*)&sAl[mr + 8][2 * tig];
            al[2] = *(const uint32_t*)&sAl[mr    ][2 * tig + 8];
            al[3] = *(const uint32_t*)&sAl[mr + 8][2 * tig + 8];
            #pragma unroll
            for (int nf = 0; nf < 4; nf++) {
                mma_bf16(acc[mf][nf], ah, blf[nf]);
                mma_bf16(acc[mf][nf], al, bhf[nf]);
                mma_bf16(acc[mf][nf], ah, bhf[nf]);
            }
        }
        __syncthreads();
    }

    // epilogue
    float* Cb = C ? C + (long long)batch * Cs_b : (float*)0;
    #pragma unroll
    for (int mf = 0; mf < 4; mf++) {
        #pragma unroll
        for (int nf = 0; nf < 4; nf++) {
            int col = n0 + wn + nf * 8 + 2 * tig;
            if (col >= N) continue;
            int row0 = m0 + wm + mf * 16 + gid;
            float v[4];
            #pragma unroll
            for (int r = 0; r < 4; r++) {
                float t = acc[mf][nf][r] * alpha;
                if (bias) t += bias[col + (r & 1)];
                if (act == 1) t = gelu_f(t);
                v[r] = t;
            }
            if (Cb) {
                Cb[(long long)row0 * Cs_m + col]           = v[0];
                Cb[(long long)row0 * Cs_m + col + 1]       = v[1];
                Cb[(long long)(row0 + 8) * Cs_m + col]     = v[2];
                Cb[(long long)(row0 + 8) * Cs_m + col + 1] = v[3];
            }
            if (Ch) {
                bf16 h0,l0,h1,l1;
                split2(v[0], h0, l0); split2(v[1], h1, l1);
                bf162 ph; ph.x = h0; ph.y = h1;
                bf162 pl; pl.x = l0; pl.y = l1;
                *(bf162*)&Ch[(long long)row0 * N + col] = ph;
                *(bf162*)&Cl[(long long)row0 * N + col] = pl;
                split2(v[2], h0, l0); split2(v[3], h1, l1);
                ph.x = h0; ph.y = h1; pl.x = l0; pl.y = l1;
                *(bf162*)&Ch[(long long)(row0 + 8) * N + col] = ph;
                *(bf162*)&Cl[(long long)(row0 + 8) * N + col] = pl;
            }
        }
    }
}

// ---------------- weight transpose + split ----------------
__global__ void wsplit_T(const float* __restrict__ w, bf16* __restrict__ oh,
                         bf16* __restrict__ ol, int K, int N) {
    __shared__ float t[32][33];
    int n0 = blockIdx.x * 32, k0 = blockIdx.y * 32;
    int tx = threadIdx.x, ty = threadIdx.y;
    #pragma unroll
    for (int j = 0; j < 32; j += 8)
        t[ty + j][tx] = w[(long)(k0 + ty + j) * N + n0 + tx];
    __syncthreads();
    #pragma unroll
    for (int j = 0; j < 32; j += 8) {
        float v = t[tx][ty + j];
        bf16 hh, ll; split2(v, hh, ll);
        long o = (long)(n0 + ty + j) * K + k0 + tx;
        oh[o] = hh; ol[o] = ll;
    }
}

// ---------------- plain vectorized split ----------------
__global__ void split_k(const float* __restrict__ in, bf16* __restrict__ oh,
                        bf16* __restrict__ ol, long n4) {
    long i = (long)blockIdx.x * 256 + threadIdx.x;
    if (i >= n4) return;
    float4 v = ((const float4*)in)[i];
    bf16 h0,l0,h1,l1,h2,l2,h3,l3;
    split2(v.x,h0,l0); split2(v.y,h1,l1); split2(v.z,h2,l2); split2(v.w,h3,l3);
    bf162 a,b;
    a.x=h0; a.y=h1; b.x=h2; b.y=h3;
    ((bf162*)oh)[i*2] = a; ((bf162*)oh)[i*2+1] = b;
    a.x=l0; a.y=l1; b.x=l2; b.y=l3;
    ((bf162*)ol)[i*2] = a; ((bf162*)ol)[i*2+1] = b;
}

// ---------------- RMSNorm (fp32 out OR split out) ----------------
__global__ void rmsnorm_k(const float* __restrict__ in, const float* __restrict__ w,
                          float* __restrict__ out, bf16* __restrict__ oh, bf16* __restrict__ ol,
                          int ncols, float eps) {
    long row = blockIdx.x;
    const float* r = in + row * (long)ncols;
    float ss = 0.f;
    for (int c = threadIdx.x; c < ncols; c += blockDim.x) { float v = r[c]; ss = fmaf(v, v, ss); }
    #pragma unroll
    for (int o = 16; o; o >>= 1) ss += __shfl_xor_sync(~0u, ss, o);
    __shared__ float sh[32];
    int wid = threadIdx.x >> 5, lane = threadIdx.x & 31;
    if (lane == 0) sh[wid] = ss;
    __syncthreads();
    int nw = blockDim.x >> 5;
    if (wid == 0) {
        ss = (lane < nw) ? sh[lane] : 0.f;
        #pragma unroll
        for (int o = 16; o; o >>= 1) ss += __shfl_xor_sync(~0u, ss, o);
        if (lane == 0) sh[0] = ss;
    }
    __syncthreads();
    float scale = rsqrtf(sh[0] / (float)ncols + eps);
    for (int c = threadIdx.x; c < ncols; c += blockDim.x) {
        float v = r[c] * scale * w[c];
        if (out) out[row * (long)ncols + c] = v;
        if (oh) { bf16 hh, ll; split2(v, hh, ll); oh[row*(long)ncols+c]=hh; ol[row*(long)ncols+c]=ll; }
    }
}

// ---------------- PGC conv3 + gate ----------------
__global__ void conv_gate_k(const float* __restrict__ xv, const float* __restrict__ cw,
                            const float* __restrict__ cb, float* __restrict__ g) {
    long bl = blockIdx.x;
    int l = (int)(bl & (Lsz - 1));
    int e = threadIdx.x;
    const float* base = xv + bl * 512;
    float xm = (l > 0)       ? base[-512 + e] : 0.f;
    float xc = base[e];
    float xp = (l < Lsz - 1) ? base[ 512 + e] : 0.f;
    float v  = base[256 + e];
    float w0 = cw[e * 3], w1 = cw[e * 3 + 1], w2 = cw[e * 3 + 2];
    float conv = fmaf(w0, xm, fmaf(w1, xc, fmaf(w2, xp, cb[e])));
    g[bl * 256 + e] = v * conv;
}

// ---------------- transpose (B,L,D) -> (B,D,L) fp32 ----------------
__global__ void transpose_LD(const float* __restrict__ in, float* __restrict__ out) {
    __shared__ float tile[32][33];
    int b = blockIdx.z;
    int l0 = blockIdx.x * 32, d0 = blockIdx.y * 32;
    #pragma unroll
    for (int j = 0; j < 32; j += 8)
        tile[threadIdx.y + j][threadIdx.x] =
            in[((long)b * Lsz + (l0 + threadIdx.y + j)) * Dsz + d0 + threadIdx.x];
    __syncthreads();
    #pragma unroll
    for (int j = 0; j < 32; j += 8)
        out[((long)b * Dsz + (d0 + threadIdx.y + j)) * Lsz + l0 + threadIdx.x] =
            tile[threadIdx.x][threadIdx.y + j];
}

// ---------------- transpose+split (B,D,L) -> (B,L,D) bf16 hi/lo ----------------
__global__ void tsplit_DL(const float* __restrict__ in, bf16* __restrict__ oh,
                          bf16* __restrict__ ol) {
    __shared__ float tile[32][33];
    int b = blockIdx.z;
    int d0 = blockIdx.x * 32, l0 = blockIdx.y * 32;
    #pragma unroll
    for (int j = 0; j < 32; j += 8)
        tile[threadIdx.y + j][threadIdx.x] =
            in[((long)b * Dsz + (d0 + threadIdx.y + j)) * Lsz + l0 + threadIdx.x];
    __syncthreads();
    #pragma unroll
    for (int j = 0; j < 32; j += 8) {
        float v = tile[threadIdx.x][threadIdx.y + j];
        bf16 hh, ll; split2(v, hh, ll);
        long o = ((long)b * Lsz + (l0 + threadIdx.y + j)) * Dsz + d0 + threadIdx.x;
        oh[o] = hh; ol[o] = ll;
    }
}

// ---------------- S4D parameter precompute ----------------
__global__ void s4_pre_k(const float* __restrict__ C_ri, const float* __restrict__ log_dt,
                         const float* __restrict__ logAr, const float* __restrict__ Aim,
                         float* __restrict__ lam_r, float* __restrict__ lam_i,
                         float* __restrict__ cm_r, float* __restrict__ cm_i) {
    int idx = blockIdx.x * blockDim.x + threadIdx.x;
    if (idx >= Dsz * 32) return;
    int h = idx >> 5;
    float dt = expf(log_dt[h]);
    float Ar = -expf(logAr[idx]);
    float Ai = Aim[idx];
    float dr = Ar * dt, di = Ai * dt;
    float er = expf(dr);
    float lr = er * cosf(di), li = er * sinf(di);
    lam_r[idx] = lr; lam_i[idx] = li;
    float Er = lr - 1.f, Ei = li;
    float den = Ar * Ar + Ai * Ai;
    float qr = (Er * Ar + Ei * Ai) / den;
    float qi = (Ei * Ar - Er * Ai) / den;
    float Cr = C_ri[idx * 2], Ci = C_ri[idx * 2 + 1];
    cm_r[idx] = Cr * qr - Ci * qi;
    cm_i[idx] = Cr * qi + Ci * qr;
}

// ---------------- S4D diagonal recurrence ----------------
__global__ void s4_scan_k(const float* __restrict__ u,
                          const float* __restrict__ lam_r, const float* __restrict__ lam_i,
                          const float* __restrict__ cm_r, const float* __restrict__ cm_i,
                          const float* __restrict__ Dp, float* __restrict__ y) {
    int gw = (blockIdx.x * blockDim.x + threadIdx.x) >> 5;
    int lane = threadIdx.x & 31;
    int b = gw >> 8, h = gw & 255;
    int idx = h * 32 + lane;
    float lr = lam_r[idx], li = lam_i[idx];
    float cr = cm_r[idx],  ci = cm_i[idx];
    float dp = Dp[h];
    const float* up = u + ((long)b * Dsz + h) * Lsz;
    float*       yp = y + ((long)b * Dsz + h) * Lsz;
    float sr = 0.f, si = 0.f;
    #pragma unroll 4
    for (int l = 0; l < Lsz; l++) {
        float uv = __ldg(up + l);
        float nsr = fmaf(lr, sr, fmaf(-li, si, uv));
        float nsi = fmaf(lr, si, li * sr);
        sr = nsr; si = nsi;
        float c = cr * sr - ci * si;
        c += __shfl_xor_sync(~0u, c, 16);
        c += __shfl_xor_sync(~0u, c, 8);
        c += __shfl_xor_sync(~0u, c, 4);
        c += __shfl_xor_sync(~0u, c, 2);
        c += __shfl_xor_sync(~0u, c, 1);
        if (lane == 0) {
            float yv = fmaf(dp, uv, 2.f * c);
            yp[l] = gelu_f(yv);
        }
    }
}

// ---------------- GLU + residual ----------------
__global__ void glu_res_k(const float* __restrict__ z, float* __restrict__ h) {
    long idx = (long)blockIdx.x * 256 + threadIdx.x;
    long row = idx >> 8;
    int o = (int)(idx & 255);
    float a = z[row * 512 + o];
    float g = z[row * 512 + 256 + o];
    h[idx] += a * (1.f / (1.f + expf(-g)));
}

// ---------------- small scalar GEMM (tiny N heads) ----------------
__global__ void gemm_small(const float* __restrict__ A, const float* __restrict__ Bm,
                           const float* __restrict__ bias, float* __restrict__ C,
                           int N, int K, long long Cs_m) {
    long m = blockIdx.x;
    int tid = threadIdx.x;
    const float* Ar = A + m * K;
    __shared__ float red[4][128];
    for (int n = 0; n < N; n++) {
        float s = 0.f;
        for (int k = tid; k < K; k += 128) s = fmaf(Ar[k], Bm[(long)k * N + n], s);
        red[n][tid] = s;
    }
    __syncthreads();
    if (tid < N) {
        float s = 0.f;
        #pragma unroll
        for (int i = 0; i < 128; i++) s += red[tid][i];
        C[m * Cs_m + tid] = s + bias[tid];
    }
}

// ---------------- unpaired column ----------------
__global__ void unpaired_k(const float* __restrict__ ub, float* __restrict__ out) {
    int idx = blockIdx.x * blockDim.x + threadIdx.x;
    out[(long)idx * 2054 + 2053] = ub[0];
}

// ---------------- host ----------------
static void gemm_bf_launch(const bf16* Ah, const bf16* Al, const bf16* Bh, const bf16* Bl,
                           const float* bias, float* C, bf16* Ch, bf16* Cl,
                           int M, int N, int K,
                           long long asb, long long bsb, long long csb, long long csm,
                           float alpha, int act, int batch) {
    dim3 grid((N + 127) / 128, M / 128, batch);
    gemm_bf<<<grid, 256>>>(Ah, Al, Bh, Bl, bias, C, Ch, Cl, M, N, K,
                           asb, bsb, csb, csm, alpha, act);
}

extern "C" void kernel_launch(void* const* d_in, const int* in_sizes, int n_in,
                              void* d_out, int out_size) {
    const float* x          = (const float*)d_in[0];
    const float* enc_w      = (const float*)d_in[1];
    const float* enc_b      = (const float*)d_in[2];
    const float* pgc_in_w   = (const float*)d_in[3];
    const float* pgc_in_b   = (const float*)d_in[4];
    const float* pgc_innorm = (const float*)d_in[5];
    const float* pgc_conv_w = (const float*)d_in[6];
    const float* pgc_conv_b = (const float*)d_in[7];
    const float* pgc_norm_w = (const float*)d_in[8];
    const float* pgc_out_w  = (const float*)d_in[9];
    const float* pgc_out_b  = (const float*)d_in[10];
    const float* s4_norm_w  = (const float*)d_in[11];
    const float* s4_Dp      = (const float*)d_in[12];
    const float* s4_C       = (const float*)d_in[13];
    const float* s4_log_dt  = (const float*)d_in[14];
    const float* s4_logAr   = (const float*)d_in[15];
    const float* s4_Aim     = (const float*)d_in[16];
    const float* s4_out_w   = (const float*)d_in[17];
    const float* s4_out_b   = (const float*)d_in[18];
    const float* db_w1      = (const float*)d_in[19];
    const float* db_b1      = (const float*)d_in[20];
    const float* db_w2      = (const float*)d_in[21];
    const float* db_b2      = (const float*)d_in[22];
    const float* bin_w1     = (const float*)d_in[23];
    const float* bin_b1     = (const float*)d_in[24];
    const float* bin_w2     = (const float*)d_in[25];
    const float* bin_b2     = (const float*)d_in[26];
    const float* q_w        = (const float*)d_in[27];
    const float* q_b        = (const float*)d_in[28];
    const float* k_w        = (const float*)d_in[29];
    const float* k_b        = (const float*)d_in[30];
    const float* ub         = (const float*)d_in[31];
    float* out = (float*)d_out;

    float *h, *b1, *b2, *b3, *b4, *lr, *li, *cr, *ci;
    bf16 *xh, *xl, *yh, *yl, *qh, *ql, *kh, *kl, *wh, *wl;
    cudaGetSymbolAddress((void**)&h,  g_h);
    cudaGetSymbolAddress((void**)&b1, g_b1);
    cudaGetSymbolAddress((void**)&b2, g_b2);
    cudaGetSymbolAddress((void**)&b3, g_b3);
    cudaGetSymbolAddress((void**)&b4, g_b4);
    cudaGetSymbolAddress((void**)&lr, g_lam_r);
    cudaGetSymbolAddress((void**)&li, g_lam_i);
    cudaGetSymbolAddress((void**)&cr, g_cm_r);
    cudaGetSymbolAddress((void**)&ci, g_cm_i);
    cudaGetSymbolAddress((void**)&xh, g_xh);
    cudaGetSymbolAddress((void**)&xl, g_xl);
    cudaGetSymbolAddress((void**)&yh, g_yh);
    cudaGetSymbolAddress((void**)&yl, g_yl);
    cudaGetSymbolAddress((void**)&qh, g_qh);
    cudaGetSymbolAddress((void**)&ql, g_ql);
    cudaGetSymbolAddress((void**)&kh, g_kh);
    cudaGetSymbolAddress((void**)&kl, g_kl);
    cudaGetSymbolAddress((void**)&wh, g_wh);
    cudaGetSymbolAddress((void**)&wl, g_wl);

    // ---- weight conversion ----
    dim3 tt(32, 8);
    for (int i = 0; i < NPGC; i++) {
        wsplit_T<<<dim3(512/32, 256/32), tt>>>(pgc_in_w + (long)i*131072,
                                               wh + OFF_PIN + (long)i*131072,
                                               wl + OFF_PIN + (long)i*131072, 256, 512);
        wsplit_T<<<dim3(256/32, 256/32), tt>>>(pgc_out_w + (long)i*65536,
                                               wh + OFF_POUT + (long)i*65536,
                                               wl + OFF_POUT + (long)i*65536, 256, 256);
    }
    split_k<<<(4*512*256/4 + 255)/256, 256>>>(s4_out_w, wh + OFF_S4, wl + OFF_S4, 4*512*256/4);
    wsplit_T<<<dim3(8, 8), tt>>>(q_w,   wh + OFF_Q,   wl + OFF_Q,   256, 256);
    wsplit_T<<<dim3(8, 8), tt>>>(k_w,   wh + OFF_K,   wl + OFF_K,   256, 256);
    wsplit_T<<<dim3(4, 8), tt>>>(db_w1, wh + OFF_DB,  wl + OFF_DB,  256, 128);
    wsplit_T<<<dim3(2, 8), tt>>>(bin_w1,wh + OFF_BIN, wl + OFF_BIN, 256, 64);

    // ---- encoder ----
    encoder_k<<<ML, 256>>>(x, enc_w, enc_b, h, xh, xl);

    // ---- PGC stack ----
    for (int i = 0; i < NPGC; i++) {
        gemm_bf_launch(xh, xl, wh + OFF_PIN + (long)i*131072, wl + OFF_PIN + (long)i*131072,
                       pgc_in_b + i*512, b1, 0, 0, ML, 512, 256, 0, 0, 0, 512, 1.f, 0, 1);
        rmsnorm_k<<<ML, 256>>>(b1, pgc_innorm + i*512, b1, 0, 0, 512, EPS_T);
        conv_gate_k<<<ML, 256>>>(b1, pgc_conv_w + i*768, pgc_conv_b + i*256, b2);
        rmsnorm_k<<<ML, 256>>>(b2, pgc_norm_w + i*256, 0, yh, yl, 256, EPS_T);
        gemm_bf_launch(yh, yl, wh + OFF_POUT + (long)i*65536, wl + OFF_POUT + (long)i*65536,
                       pgc_out_b + i*256, h, xh, xl, ML, 256, 256, 0, 0, 0, 256, 1.f, 0, 1);
    }

    // ---- S4D stack ----
    for (int i = 0; i < NS4; i++) {
        s4_pre_k<<<32, 256>>>(s4_C + (long)i*16384, s4_log_dt + i*256,
                              s4_logAr + (long)i*8192, s4_Aim + (long)i*8192,
                              lr, li, cr, ci);
        rmsnorm_k<<<ML, 256>>>(h, s4_norm_w + i*256, b2, 0, 0, 256, EPS_C);
        transpose_LD<<<dim3(Lsz/32, Dsz/32, Bsz), tt>>>(b2, b3);
        s4_scan_k<<<(Bsz * Dsz) / 4, 128>>>(b3, lr, li, cr, ci, s4_Dp + i*256, b4);
        tsplit_DL<<<dim3(Dsz/32, Lsz/32, Bsz), tt>>>(b4, xh, xl);
        gemm_bf_launch(xh, xl, wh + OFF_S4 + (long)i*131072, wl + OFF_S4 + (long)i*131072,
                       s4_out_b + i*512, b1, 0, 0, ML, 512, 256, 0, 0, 0, 512, 1.f, 0, 1);
        glu_res_k<<<ML, 256>>>(b1, h);
    }

    // final h split for heads
    split_k<<<(ML*256/4 + 255)/256, 256>>>(h, xh, xl, (long)ML*256/4);

    // ---- heads ----
    gemm_bf_launch(xh, xl, wh + OFF_DB, wl + OFF_DB, db_b1, b1, 0, 0,
                   ML, 128, 256, 0, 0, 0, 128, 1.f, 1, 1);
    gemm_small<<<ML, 128>>>(b1, db_w2, db_b2, out, 3, 128, 2054);
    gemm_bf_launch(xh, xl, wh + OFF_BIN, wl + OFF_BIN, bin_b1, b1, 0, 0,
                   ML, 64, 256, 0, 0, 0, 64, 1.f, 1, 1);
    gemm_small<<<ML, 128>>>(b1, bin_w2, bin_b2, out + 3, 2, 64, 2054);
    gemm_bf_launch(xh, xl, wh + OFF_Q, wl + OFF_Q, q_b, 0, qh, ql,
                   ML, 256, 256, 0, 0, 0, 256, 1.f, 0, 1);
    gemm_bf_launch(xh, xl, wh + OFF_K, wl + OFF_K, k_b, 0, kh, kl,
                   ML, 256, 256, 0, 0, 0, 256, 1.f, 0, 1);
    // scores = q @ k^T / 16 -> out[:, :, 5:5+2048], batched
    gemm_bf_launch(qh, ql, kh, kl, 0, out + 5, 0, 0,
                   Lsz, Lsz, 256,
                   (long long)Lsz*256, (long long)Lsz*256, (long long)Lsz*2054, 2054,
                   0.0625f, 0, Bsz);
    unpaired_k<<<ML/256, 256>>>(ub, out);
}